// round 3
// baseline (speedup 1.0000x reference)
#include <cuda_runtime.h>
#include <math.h>

#define Bc   16
#define Mc   256
#define Nc   512
#define H1c  16
#define H2c  8
#define Uc   8
#define OUTc 4
#define BNc  (Bc*Nc)

typedef unsigned long long ull;

// ---- packed f32x2 helpers (sm_100+) ----
__device__ __forceinline__ ull pk2(float lo, float hi) {
    ull r; asm("mov.b64 %0, {%1, %2};" : "=l"(r) : "f"(lo), "f"(hi)); return r;
}
__device__ __forceinline__ float2 upk2(ull v) {
    float2 r; asm("mov.b64 {%0, %1}, %2;" : "=f"(r.x), "=f"(r.y) : "l"(v)); return r;
}
__device__ __forceinline__ ull ffma2(ull a, ull b, ull c) {
    ull d; asm("fma.rn.f32x2 %0, %1, %2, %3;" : "=l"(d) : "l"(a), "l"(b), "l"(c)); return d;
}
__device__ __forceinline__ ull fadd2(ull a, ull b) {
    ull d; asm("add.rn.f32x2 %0, %1, %2;" : "=l"(d) : "l"(a), "l"(b)); return d;
}

__device__ __forceinline__ float sigmoidf_fast(float x) {
    return __fdividef(1.f, 1.f + __expf(-x));
}
__device__ __forceinline__ float tanhf_fast(float x) {
    float e = __expf(2.f * x);
    return 1.f - __fdividef(2.f, e + 1.f);
}

// ---- scratch (static device globals; no allocation) ----
__device__ float g_G[(size_t)Bc*Nc*Nc];   // 16 MB Gram
__device__ float g_u[BNc*Uc];
__device__ float g_g[BNc*H1c];
__device__ float g_a[BNc*H1c];            // a_i = W1_ui u_i + b1 + w1s*sigma2
__device__ float g_c[BNc*H1c];            // c_j = W1_uj u_j
__device__ float g_h2s[BNc*H2c];          // sum_j relu(h2)

// ============================================================
// K1: G = A^T A, symmetric upper tiles, f32x2 packed over k.
// 64x64 tile, 256 threads, 4x4 micro, smem stored TRANSPOSED
// (col-major) so k-pairs are contiguous 64-bit operands.
// ============================================================
__global__ void __launch_bounds__(256) gram_kernel(const float* __restrict__ A) {
    int b = blockIdx.y;
    int idx = blockIdx.x;                 // 0..35 -> (ti<=tj)
    int ti = 0;
    while (idx >= 8 - ti) { idx -= 8 - ti; ti++; }
    int tj = ti + idx;

    const float* Ab = A + (size_t)b * Mc * Nc;
    __shared__ __align__(16) float sAT[64][20];   // [col][k], pad 20
    __shared__ __align__(16) float sBT[64][20];

    int tid = threadIdx.x;
    int tx = tid & 15, ty = tid >> 4;
    int i0 = ti * 64, j0 = tj * 64;
    int lr = ty, lc = tx * 4;

    ull acc2[4][4];
#pragma unroll
    for (int r_ = 0; r_ < 4; r_++)
#pragma unroll
        for (int s_ = 0; s_ < 4; s_++) acc2[r_][s_] = 0ull;

    for (int k0 = 0; k0 < Mc; k0 += 16) {
        float4 av = *(const float4*)(Ab + (size_t)(k0 + lr) * Nc + i0 + lc);
        float4 bv = *(const float4*)(Ab + (size_t)(k0 + lr) * Nc + j0 + lc);
        __syncthreads();
        sAT[lc+0][lr] = av.x; sAT[lc+1][lr] = av.y;
        sAT[lc+2][lr] = av.z; sAT[lc+3][lr] = av.w;
        sBT[lc+0][lr] = bv.x; sBT[lc+1][lr] = bv.y;
        sBT[lc+2][lr] = bv.z; sBT[lc+3][lr] = bv.w;
        __syncthreads();
#pragma unroll
        for (int kc = 0; kc < 16; kc += 4) {
            ull aP[4][2], bP[4][2];
#pragma unroll
            for (int r_ = 0; r_ < 4; r_++) {
                ulonglong2 t = *(const ulonglong2*)&sAT[ty * 4 + r_][kc];
                aP[r_][0] = t.x; aP[r_][1] = t.y;
            }
#pragma unroll
            for (int s_ = 0; s_ < 4; s_++) {
                ulonglong2 t = *(const ulonglong2*)&sBT[tx * 4 + s_][kc];
                bP[s_][0] = t.x; bP[s_][1] = t.y;
            }
#pragma unroll
            for (int r_ = 0; r_ < 4; r_++)
#pragma unroll
                for (int s_ = 0; s_ < 4; s_++) {
                    acc2[r_][s_] = ffma2(aP[r_][0], bP[s_][0], acc2[r_][s_]);
                    acc2[r_][s_] = ffma2(aP[r_][1], bP[s_][1], acc2[r_][s_]);
                }
        }
    }

    float acc[4][4];
#pragma unroll
    for (int r_ = 0; r_ < 4; r_++)
#pragma unroll
        for (int s_ = 0; s_ < 4; s_++) {
            float2 t = upk2(acc2[r_][s_]);
            acc[r_][s_] = t.x + t.y;
        }

    float* Gb = g_G + (size_t)b * Nc * Nc;
#pragma unroll
    for (int r_ = 0; r_ < 4; r_++) {
        float4 v = make_float4(acc[r_][0], acc[r_][1], acc[r_][2], acc[r_][3]);
        *(float4*)(Gb + (size_t)(i0 + ty * 4 + r_) * Nc + j0 + tx * 4) = v;
    }
    if (ti != tj) {
#pragma unroll
        for (int s_ = 0; s_ < 4; s_++) {
            float4 v = make_float4(acc[0][s_], acc[1][s_], acc[2][s_], acc[3][s_]);
            *(float4*)(Gb + (size_t)(j0 + tx * 4 + s_) * Nc + i0 + ty * 4) = v;
        }
    }
}

// ============================================================
// K2: ATy, diag(G), u0; zero g; compute a,c (layer-1 factorization).
// ============================================================
__global__ void init_kernel(const float* __restrict__ A, const float* __restrict__ y,
                            const float* __restrict__ sigma2,
                            const float* __restrict__ w_init, const float* __restrict__ b_init,
                            const float* __restrict__ w_p1, const float* __restrict__ b_p1) {
    int b = blockIdx.y;
    int n = blockIdx.x * 128 + threadIdx.x;
    __shared__ float sy[Mc];
    for (int m = threadIdx.x; m < Mc; m += 128) sy[m] = y[b * Mc + m];
    __syncthreads();

    const float* Ab = A + (size_t)b * Mc * Nc + n;
    float aty = 0.f;
#pragma unroll 8
    for (int m = 0; m < Mc; m++) aty = fmaf(Ab[(size_t)m * Nc], sy[m], aty);

    float diag = g_G[(size_t)b * Nc * Nc + (size_t)n * Nc + n];
    float sig = sigma2[b];
    int node = b * Nc + n;

    float u[Uc];
#pragma unroll
    for (int o = 0; o < Uc; o++) {
        u[o] = b_init[o] + w_init[o * 3 + 0] * aty + w_init[o * 3 + 1] * diag
             + w_init[o * 3 + 2] * sig;
        g_u[node * Uc + o] = u[o];
    }
#pragma unroll
    for (int k = 0; k < H1c; k++) g_g[node * H1c + k] = 0.f;

#pragma unroll
    for (int o = 0; o < H1c; o++) {
        float av = b_p1[o] + w_p1[o * 18 + 17] * sig;
        float cv = 0.f;
#pragma unroll
        for (int k = 0; k < Uc; k++) {
            av = fmaf(w_p1[o * 18 + k], u[k], av);
            cv = fmaf(w_p1[o * 18 + 8 + k], u[k], cv);
        }
        g_a[node * H1c + o] = av;
        g_c[node * H1c + o] = cv;
    }
}

// ============================================================
// K4: pair kernel, f32x2 packed over k (16 -> 8 pairs).
// Block = 16 i x 16 j-lanes. Per pair: h1 = relu(a_i + c_j + w1g*G),
// acc += relu(W2 h1 + b2); diagonal included then subtracted.
// ============================================================
__global__ void __launch_bounds__(256, 1)
pair_kernel(const float* __restrict__ w_p1, const float* __restrict__ w_p2,
            const float* __restrict__ b_p2) {
    int b = blockIdx.y;
    int i0 = blockIdx.x * 16;
    int tid = threadIdx.x;
    int iy = tid >> 4, jx = tid & 15;
    int i = i0 + iy;
    int nodei = b * Nc + i;

    __shared__ __align__(16) float cS[128][20];

    // hoisted packed operands
    ull a2[8], w1g2[8], W2p[8][8], b2p[8];
    {
        const ull* ap = (const ull*)(g_a + (size_t)nodei * 16);
#pragma unroll
        for (int q = 0; q < 8; q++) a2[q] = ap[q];
#pragma unroll
        for (int q = 0; q < 8; q++)
            w1g2[q] = pk2(__ldg(&w_p1[(2*q) * 18 + 16]), __ldg(&w_p1[(2*q+1) * 18 + 16]));
        const ull* wp = (const ull*)w_p2;
#pragma unroll
        for (int o = 0; o < 8; o++) {
            b2p[o] = pk2(__ldg(&b_p2[o]), 0.f);
#pragma unroll
            for (int q = 0; q < 8; q++) W2p[o][q] = wp[o * 8 + q];
        }
    }
    float acc[8] = {0,0,0,0,0,0,0,0};
    float dacc[8] = {0,0,0,0,0,0,0,0};    // diagonal contribution to subtract

    const float* Grow = g_G + (size_t)b * Nc * Nc + (size_t)i * Nc;
    const float* cbase = g_c + (size_t)(b * Nc) * 16;

    for (int jc = 0; jc < Nc; jc += 128) {
        __syncthreads();
        {
            const float4* src = (const float4*)(cbase + (size_t)jc * 16);
            float4 v0 = src[tid];
            float4 v1 = src[tid + 256];
            *(float4*)&cS[tid >> 2][(tid & 3) * 4] = v0;
            *(float4*)&cS[(tid + 256) >> 2][(tid & 3) * 4] = v1;
        }
        __syncthreads();
#pragma unroll
        for (int s = 0; s < 8; s++) {
            int jj = jx + s * 16;
            int j = jc + jj;
            float Gv = Grow[j];
            ull G2 = pk2(Gv, Gv);
            ulonglong2 cA = *(const ulonglong2*)&cS[jj][0];
            ulonglong2 cB = *(const ulonglong2*)&cS[jj][4];
            ulonglong2 cC = *(const ulonglong2*)&cS[jj][8];
            ulonglong2 cD = *(const ulonglong2*)&cS[jj][12];
            ull c2[8] = {cA.x, cA.y, cB.x, cB.y, cC.x, cC.y, cD.x, cD.y};

            ull h1p[8];
#pragma unroll
            for (int q = 0; q < 8; q++) {
                ull t = fadd2(ffma2(w1g2[q], G2, a2[q]), c2[q]);
                float2 h = upk2(t);
                h.x = fmaxf(h.x, 0.f);
                h.y = fmaxf(h.y, 0.f);
                h1p[q] = pk2(h.x, h.y);
            }

            float v[8];
#pragma unroll
            for (int o = 0; o < 8; o++) {
                ull t = b2p[o];
#pragma unroll
                for (int q = 0; q < 8; q++) t = ffma2(W2p[o][q], h1p[q], t);
                float2 tf = upk2(t);
                v[o] = fmaxf(tf.x + tf.y, 0.f);
            }
            if (j == i) {
#pragma unroll
                for (int o = 0; o < 8; o++) dacc[o] = v[o];
            }
#pragma unroll
            for (int o = 0; o < 8; o++) acc[o] += v[o];
        }
    }

#pragma unroll
    for (int o = 0; o < 8; o++) {
        acc[o] -= dacc[o];
#pragma unroll
        for (int off = 8; off; off >>= 1)
            acc[o] += __shfl_down_sync(0xffffffffu, acc[o], off, 16);
    }
    if (jx == 0) {
#pragma unroll
        for (int o = 0; o < 8; o++) g_h2s[nodei * 8 + o] = acc[o];
    }
}

// ============================================================
// K5: GRU: 16 threads per node (one per gate), 16 nodes per
// 256-thread block, padded smem weights, fast math.
// GRID MUST BE BNc/16 BLOCKS.
// ============================================================
__global__ void __launch_bounds__(256) gru_kernel(
        const float* __restrict__ w_p3, const float* __restrict__ b_p3,
        const float* __restrict__ w_ih, const float* __restrict__ b_ih,
        const float* __restrict__ w_hh, const float* __restrict__ b_hh,
        const float* __restrict__ w_up, const float* __restrict__ b_up,
        const float* __restrict__ w_p1, const float* __restrict__ b_p1,
        const float* __restrict__ r, const float* __restrict__ Sigma,
        const float* __restrict__ sigma2) {
    __shared__ float s_wih[480];          // rows of 10 (conflict-free)
    __shared__ float s_whh[48 * 17];      // pad 16->17
    __shared__ float s_wp3[8 * 9];        // pad 8->9
    __shared__ float s_wup[8 * 17];       // pad 16->17
    __shared__ float s_wp1[288];          // rows of 18 (conflict-free)
    __shared__ float s_bih[48], s_bhh[48], s_bp3[8], s_bup[8], s_bp1[16];
    __shared__ float sgin[16][10], sg[16][17], sgn[16][17], su[16][8];

    int tid = threadIdx.x;
    for (int t = tid; t < 480; t += 256) s_wih[t] = w_ih[t];
    for (int t = tid; t < 768; t += 256) s_whh[(t >> 4) * 17 + (t & 15)] = w_hh[t];
    for (int t = tid; t < 288; t += 256) s_wp1[t] = w_p1[t];
    if (tid < 128) s_wup[(tid >> 4) * 17 + (tid & 15)] = w_up[tid];
    if (tid < 64)  s_wp3[(tid >> 3) * 9 + (tid & 7)] = w_p3[tid];
    if (tid < 48)  { s_bih[tid] = b_ih[tid]; s_bhh[tid] = b_hh[tid]; }
    if (tid < 16)  s_bp1[tid] = b_p1[tid];
    if (tid < 8)   { s_bp3[tid] = b_p3[tid]; s_bup[tid] = b_up[tid]; }
    __syncthreads();

    int nl = tid >> 4, t = tid & 15;
    int node = blockIdx.x * 16 + nl;
    int b = node >> 9;                    // node / Nc

    // phase 0: stage g; compute gru input (m_sum via W3, plus r/Sigma)
    sg[nl][t] = g_g[node * 16 + t];
    if (t < 8) {
        float m = s_bp3[t] * (float)(Nc - 1);
#pragma unroll
        for (int q = 0; q < 8; q++)
            m = fmaf(s_wp3[t * 9 + q], g_h2s[node * 8 + q], m);
        sgin[nl][t] = m;
    } else if (t == 8) {
        sgin[nl][8] = r[node];
    } else if (t == 9) {
        sgin[nl][9] = Sigma[node];
    }
    __syncthreads();

    // phase 1: one gate per thread
    {
        float ir = s_bih[t],      hr = s_bhh[t];
        float iz = s_bih[16 + t], hz = s_bhh[16 + t];
        float in_ = s_bih[32 + t], hn = s_bhh[32 + t];
#pragma unroll
        for (int k = 0; k < 10; k++) {
            float x = sgin[nl][k];
            ir  = fmaf(s_wih[t * 10 + k],        x, ir);
            iz  = fmaf(s_wih[(16 + t) * 10 + k], x, iz);
            in_ = fmaf(s_wih[(32 + t) * 10 + k], x, in_);
        }
#pragma unroll
        for (int k = 0; k < 16; k++) {
            float x = sg[nl][k];
            hr = fmaf(s_whh[t * 17 + k],        x, hr);
            hz = fmaf(s_whh[(16 + t) * 17 + k], x, hz);
            hn = fmaf(s_whh[(32 + t) * 17 + k], x, hn);
        }
        float rr = sigmoidf_fast(ir + hr);
        float zz = sigmoidf_fast(iz + hz);
        float nn = tanhf_fast(in_ + rr * hn);
        float gv = sg[nl][t];
        float gn = (1.f - zz) * nn + zz * gv;
        sgn[nl][t] = gn;
        g_g[node * 16 + t] = gn;
    }
    __syncthreads();

    // phase 2: u = W_up g + b  (8 outputs per node)
    if (t < 8) {
        float uv = s_bup[t];
#pragma unroll
        for (int k = 0; k < 16; k++) uv = fmaf(s_wup[t * 17 + k], sgn[nl][k], uv);
        su[nl][t] = uv;
        g_u[node * 8 + t] = uv;
    }
    __syncthreads();

    // phase 3: a,c for the next pair layer (16 outputs per node)
    {
        float sig = sigma2[b];
        float av = s_bp1[t] + s_wp1[t * 18 + 17] * sig;
        float cv = 0.f;
#pragma unroll
        for (int k = 0; k < 8; k++) {
            float uv = su[nl][k];
            av = fmaf(s_wp1[t * 18 + k], uv, av);
            cv = fmaf(s_wp1[t * 18 + 8 + k], uv, cv);
        }
        g_a[node * 16 + t] = av;
        g_c[node * 16 + t] = cv;
    }
}

// ============================================================
// K6: readout MLP + softmax; emit (probs, u, g).
// ============================================================
__global__ void readout_kernel(const float* __restrict__ w_r1, const float* __restrict__ b_r1,
                               const float* __restrict__ w_r2, const float* __restrict__ b_r2,
                               const float* __restrict__ w_r3, const float* __restrict__ b_r3,
                               float* __restrict__ out) {
    __shared__ float s_w1[128], s_b1[16], s_w2[128], s_b2[8], s_w3[32], s_b3[4];
    int tid = threadIdx.x;
    if (tid < 128) { s_w1[tid] = w_r1[tid]; s_w2[tid] = w_r2[tid]; }
    if (tid < 32) s_w3[tid] = w_r3[tid];
    if (tid < 16) s_b1[tid] = b_r1[tid];
    if (tid < 8)  s_b2[tid] = b_r2[tid];
    if (tid < 4)  s_b3[tid] = b_r3[tid];
    __syncthreads();

    int node = blockIdx.x * 128 + tid;

    float u[8];
#pragma unroll
    for (int o = 0; o < 8; o++) u[o] = g_u[node * 8 + o];

    float h1[16];
#pragma unroll
    for (int t = 0; t < 16; t++) {
        float a = s_b1[t];
#pragma unroll
        for (int k = 0; k < 8; k++) a = fmaf(s_w1[t * 8 + k], u[k], a);
        h1[t] = fmaxf(a, 0.f);
    }
    float h2[8];
#pragma unroll
    for (int t = 0; t < 8; t++) {
        float a = s_b2[t];
#pragma unroll
        for (int k = 0; k < 16; k++) a = fmaf(s_w2[t * 16 + k], h1[k], a);
        h2[t] = fmaxf(a, 0.f);
    }
    float lg[4];
#pragma unroll
    for (int t = 0; t < 4; t++) {
        float a = s_b3[t];
#pragma unroll
        for (int k = 0; k < 8; k++) a = fmaf(s_w3[t * 8 + k], h2[k], a);
        lg[t] = a;
    }
    float mx = fmaxf(fmaxf(lg[0], lg[1]), fmaxf(lg[2], lg[3]));
    float e0 = __expf(lg[0] - mx), e1 = __expf(lg[1] - mx),
          e2 = __expf(lg[2] - mx), e3 = __expf(lg[3] - mx);
    float inv = __fdividef(1.f, e0 + e1 + e2 + e3);

    out[node * 4 + 0] = e0 * inv;
    out[node * 4 + 1] = e1 * inv;
    out[node * 4 + 2] = e2 * inv;
    out[node * 4 + 3] = e3 * inv;
#pragma unroll
    for (int o = 0; o < 8; o++) out[BNc * 4 + node * 8 + o] = u[o];
#pragma unroll
    for (int k = 0; k < 16; k++) out[BNc * 12 + node * 16 + k] = g_g[node * 16 + k];
}

// ============================================================
extern "C" void kernel_launch(void* const* d_in, const int* in_sizes, int n_in,
                              void* d_out, int out_size) {
    const float* y      = (const float*)d_in[0];
    const float* A      = (const float*)d_in[1];
    const float* sigma2 = (const float*)d_in[2];
    const float* r      = (const float*)d_in[3];
    const float* Sigma  = (const float*)d_in[4];
    const float* w_init = (const float*)d_in[5];
    const float* b_init = (const float*)d_in[6];
    const float* w_p1   = (const float*)d_in[7];
    const float* b_p1   = (const float*)d_in[8];
    const float* w_p2   = (const float*)d_in[9];
    const float* b_p2   = (const float*)d_in[10];
    const float* w_p3   = (const float*)d_in[11];
    const float* b_p3   = (const float*)d_in[12];
    const float* w_ih   = (const float*)d_in[13];
    const float* b_ih   = (const float*)d_in[14];
    const float* w_hh   = (const float*)d_in[15];
    const float* b_hh   = (const float*)d_in[16];
    const float* w_up   = (const float*)d_in[17];
    const float* b_up   = (const float*)d_in[18];
    const float* w_r1   = (const float*)d_in[19];
    const float* b_r1   = (const float*)d_in[20];
    const float* w_r2   = (const float*)d_in[21];
    const float* b_r2   = (const float*)d_in[22];
    const float* w_r3   = (const float*)d_in[23];
    const float* b_r3   = (const float*)d_in[24];

    gram_kernel<<<dim3(36, Bc), 256>>>(A);
    init_kernel<<<dim3(Nc / 128, Bc), 128>>>(A, y, sigma2, w_init, b_init, w_p1, b_p1);
    for (int l = 0; l < 2; l++) {
        pair_kernel<<<dim3(Nc / 16, Bc), 256>>>(w_p1, w_p2, b_p2);
        // 16 nodes per block (16 threads/node, 256 threads) -> BNc/16 blocks
        gru_kernel<<<BNc / 16, 256>>>(w_p3, b_p3, w_ih, b_ih, w_hh, b_hh,
                                      w_up, b_up, w_p1, b_p1, r, Sigma, sigma2);
    }
    readout_kernel<<<BNc / 128, 128>>>(w_r1, b_r1, w_r2, b_r2, w_r3, b_r3,
                                       (float*)d_out);
}

// round 5
// speedup vs baseline: 1.4604x; 1.4604x over previous
#include <cuda_runtime.h>
#include <math.h>

#define Bc   16
#define Mc   256
#define Nc   512
#define H1c  16
#define H2c  8
#define Uc   8
#define OUTc 4
#define BNc  (Bc*Nc)

__device__ __forceinline__ float sigmoidf_fast(float x) {
    return __fdividef(1.f, 1.f + __expf(-x));
}
__device__ __forceinline__ float tanhf_fast(float x) {
    float e = __expf(2.f * x);
    return 1.f - __fdividef(2.f, e + 1.f);
}

// ---- scratch (static device globals; no allocation) ----
__device__ float g_G[(size_t)Bc*Nc*Nc];     // 16 MB Gram
__device__ float g_g[BNc*H1c];              // GRU hidden
__device__ float g_ab[2][BNc*H1c];          // a_i per layer buffer
__device__ float g_cb[2][BNc*H1c];          // c_j per layer buffer

// ============================================================
// K1: G = A^T A per batch, symmetric upper-triangular tiles.
// 64x64 tile, 256 threads, 4x4 micro-tile, K-chunk 16. (Round-1 proven)
// ============================================================
__global__ void __launch_bounds__(256) gram_kernel(const float* __restrict__ A) {
    int b = blockIdx.y;
    int idx = blockIdx.x;                 // 0..35 -> (ti<=tj) of 8x8 tiles
    int ti = 0;
    while (idx >= 8 - ti) { idx -= 8 - ti; ti++; }
    int tj = ti + idx;

    const float* Ab = A + (size_t)b * Mc * Nc;
    __shared__ __align__(16) float sA[16][68];
    __shared__ __align__(16) float sB[16][68];

    int tid = threadIdx.x;
    int tx = tid & 15, ty = tid >> 4;
    int i0 = ti * 64, j0 = tj * 64;
    int lr = ty, lc = tx * 4;

    float acc[4][4];
#pragma unroll
    for (int r_ = 0; r_ < 4; r_++)
#pragma unroll
        for (int s_ = 0; s_ < 4; s_++) acc[r_][s_] = 0.f;

    for (int k0 = 0; k0 < Mc; k0 += 16) {
        float4 av = *(const float4*)(Ab + (size_t)(k0 + lr) * Nc + i0 + lc);
        float4 bv = *(const float4*)(Ab + (size_t)(k0 + lr) * Nc + j0 + lc);
        __syncthreads();
        *(float4*)&sA[lr][lc] = av;
        *(float4*)&sB[lr][lc] = bv;
        __syncthreads();
#pragma unroll
        for (int k = 0; k < 16; k++) {
            float4 a4 = *(const float4*)&sA[k][ty * 4];
            float4 b4 = *(const float4*)&sB[k][tx * 4];
            float ar[4] = {a4.x, a4.y, a4.z, a4.w};
            float br[4] = {b4.x, b4.y, b4.z, b4.w};
#pragma unroll
            for (int r_ = 0; r_ < 4; r_++)
#pragma unroll
                for (int s_ = 0; s_ < 4; s_++)
                    acc[r_][s_] = fmaf(ar[r_], br[s_], acc[r_][s_]);
        }
    }

    float* Gb = g_G + (size_t)b * Nc * Nc;
#pragma unroll
    for (int r_ = 0; r_ < 4; r_++) {
        float4 v = make_float4(acc[r_][0], acc[r_][1], acc[r_][2], acc[r_][3]);
        *(float4*)(Gb + (size_t)(i0 + ty * 4 + r_) * Nc + j0 + tx * 4) = v;
    }
    if (ti != tj) {                       // mirror into lower triangle
#pragma unroll
        for (int s_ = 0; s_ < 4; s_++) {
            float4 v = make_float4(acc[0][s_], acc[1][s_], acc[2][s_], acc[3][s_]);
            *(float4*)(Gb + (size_t)(j0 + tx * 4 + s_) * Nc + i0 + ty * 4) = v;
        }
    }
}

// ============================================================
// K2: ATy, diag(G), u0; zero g; a,c -> buffer 0. (Round-1 proven)
// ============================================================
__global__ void init_kernel(const float* __restrict__ A, const float* __restrict__ y,
                            const float* __restrict__ sigma2,
                            const float* __restrict__ w_init, const float* __restrict__ b_init,
                            const float* __restrict__ w_p1, const float* __restrict__ b_p1) {
    int b = blockIdx.y;
    int n = blockIdx.x * 128 + threadIdx.x;
    __shared__ float sy[Mc];
    for (int m = threadIdx.x; m < Mc; m += 128) sy[m] = y[b * Mc + m];
    __syncthreads();

    const float* Ab = A + (size_t)b * Mc * Nc + n;
    float aty = 0.f;
#pragma unroll 8
    for (int m = 0; m < Mc; m++) aty = fmaf(Ab[(size_t)m * Nc], sy[m], aty);

    float diag = g_G[(size_t)b * Nc * Nc + (size_t)n * Nc + n];
    float sig = sigma2[b];
    int node = b * Nc + n;

    float u[Uc];
#pragma unroll
    for (int o = 0; o < Uc; o++) {
        u[o] = b_init[o] + w_init[o * 3 + 0] * aty + w_init[o * 3 + 1] * diag
             + w_init[o * 3 + 2] * sig;
    }
#pragma unroll
    for (int k = 0; k < H1c; k++) g_g[node * H1c + k] = 0.f;

#pragma unroll
    for (int o = 0; o < H1c; o++) {
        float av = b_p1[o] + w_p1[o * 18 + 17] * sig;
        float cv = 0.f;
#pragma unroll
        for (int k = 0; k < Uc; k++) {
            av = fmaf(w_p1[o * 18 + k], u[k], av);
            cv = fmaf(w_p1[o * 18 + 8 + k], u[k], cv);
        }
        g_ab[0][node * H1c + o] = av;
        g_cb[0][node * H1c + o] = cv;
    }
}

// ============================================================
// K3: fused pair + GRU (+ readout on last layer).
// Block = 16 i x 16 j-lanes (256 thr). Main loop = Round-1 proven.
// Epilogue = Round-3 proven GRU (16 thr/node), h2s via smem.
// a/c double-buffered: read buf (layer&1), write buf (1-(layer&1)).
// ============================================================
__global__ void __launch_bounds__(256, 1)
pair_fused(const float* __restrict__ w_p1, const float* __restrict__ b_p1,
           const float* __restrict__ w_p2, const float* __restrict__ b_p2,
           const float* __restrict__ w_p3, const float* __restrict__ b_p3,
           const float* __restrict__ w_ih, const float* __restrict__ b_ih,
           const float* __restrict__ w_hh, const float* __restrict__ b_hh,
           const float* __restrict__ w_up, const float* __restrict__ b_up,
           const float* __restrict__ r, const float* __restrict__ Sigma,
           const float* __restrict__ sigma2,
           const float* __restrict__ w_r1, const float* __restrict__ b_r1,
           const float* __restrict__ w_r2, const float* __restrict__ b_r2,
           const float* __restrict__ w_r3, const float* __restrict__ b_r3,
           float* __restrict__ out, int layer) {
    int rd = layer & 1;
    int wr = 1 - rd;
    int last = (layer == 1);

    int b = blockIdx.y;
    int i0 = blockIdx.x * 16;
    int tid = threadIdx.x;
    int iy = tid >> 4, jx = tid & 15;
    int i = i0 + iy;
    int nodei = b * Nc + i;

    __shared__ __align__(16) float cS[128][20];
    // --- epilogue weights/state ---
    __shared__ float s_wih[480], s_whh[48 * 17], s_wp3[8 * 9], s_wup[8 * 17], s_wp1[288];
    __shared__ float s_bih[48], s_bhh[48], s_bp3[8], s_bup[8], s_bp1[16];
    __shared__ float s_h2s[16][8];
    __shared__ float sgin[16][10], sg[16][17], sgn[16][17], su[16][8];
    __shared__ float s_r1[128], s_br1[16], s_r2[128], s_br2[8], s_r3[32], s_br3[4];
    __shared__ float sh1[16][17];

    // stage epilogue weights (read only after later __syncthreads)
    for (int t = tid; t < 480; t += 256) s_wih[t] = w_ih[t];
    for (int t = tid; t < 768; t += 256) s_whh[(t >> 4) * 17 + (t & 15)] = w_hh[t];
    for (int t = tid; t < 288; t += 256) s_wp1[t] = w_p1[t];
    if (tid < 128) s_wup[(tid >> 4) * 17 + (tid & 15)] = w_up[tid];
    if (tid < 64)  s_wp3[(tid >> 3) * 9 + (tid & 7)] = w_p3[tid];
    if (tid < 48)  { s_bih[tid] = b_ih[tid]; s_bhh[tid] = b_hh[tid]; }
    if (tid < 16)  s_bp1[tid] = b_p1[tid];
    if (tid < 8)   { s_bp3[tid] = b_p3[tid]; s_bup[tid] = b_up[tid]; }
    if (last) {
        if (tid < 128) { s_r1[tid] = w_r1[tid]; s_r2[tid] = w_r2[tid]; }
        if (tid < 32) s_r3[tid] = w_r3[tid];
        if (tid < 16) s_br1[tid] = b_r1[tid];
        if (tid < 8)  s_br2[tid] = b_r2[tid];
        if (tid < 4)  s_br3[tid] = b_r3[tid];
    }

    // --- hoisted per-i operands (Round-1 pattern) ---
    float areg[16], w1g[16], W2[8][16], b2r[8];
#pragma unroll
    for (int k = 0; k < 16; k++) areg[k] = g_ab[rd][nodei * 16 + k];
#pragma unroll
    for (int k = 0; k < 16; k++) w1g[k] = __ldg(&w_p1[k * 18 + 16]);
#pragma unroll
    for (int o = 0; o < 8; o++) {
        b2r[o] = __ldg(&b_p2[o]);
#pragma unroll
        for (int k = 0; k < 16; k++) W2[o][k] = __ldg(&w_p2[o * 16 + k]);
    }
    float acc[8] = {0.f, 0.f, 0.f, 0.f, 0.f, 0.f, 0.f, 0.f};

    const float* Grow = g_G + (size_t)b * Nc * Nc + (size_t)i * Nc;
    const float* cbase = g_cb[rd] + (size_t)(b * Nc) * 16;

    for (int jc = 0; jc < Nc; jc += 128) {
        __syncthreads();
        {
            const float4* src = (const float4*)(cbase + (size_t)jc * 16);
            float4 v0 = src[tid];
            float4 v1 = src[tid + 256];
            *(float4*)&cS[tid >> 2][(tid & 3) * 4] = v0;
            *(float4*)&cS[(tid + 256) >> 2][(tid & 3) * 4] = v1;
        }
        __syncthreads();
#pragma unroll
        for (int s = 0; s < 8; s++) {
            int jj = jx + s * 16;
            int j = jc + jj;
            float Gv = Grow[j];
            float4 c0 = *(const float4*)&cS[jj][0];
            float4 c1 = *(const float4*)&cS[jj][4];
            float4 c2 = *(const float4*)&cS[jj][8];
            float4 c3 = *(const float4*)&cS[jj][12];
            float cv[16] = {c0.x, c0.y, c0.z, c0.w, c1.x, c1.y, c1.z, c1.w,
                            c2.x, c2.y, c2.z, c2.w, c3.x, c3.y, c3.z, c3.w};
            float h1[16];
#pragma unroll
            for (int k = 0; k < 16; k++)
                h1[k] = fmaxf(fmaf(w1g[k], Gv, areg[k]) + cv[k], 0.f);
            float mask = (j == i) ? 0.f : 1.f;
#pragma unroll
            for (int o = 0; o < 8; o++) {
                float t2 = b2r[o];
#pragma unroll
                for (int k = 0; k < 16; k++) t2 = fmaf(W2[o][k], h1[k], t2);
                acc[o] = fmaf(mask, fmaxf(t2, 0.f), acc[o]);
            }
        }
    }

    // reduce across the 16 j-lanes of this i -> smem
#pragma unroll
    for (int o = 0; o < 8; o++) {
#pragma unroll
        for (int off = 8; off; off >>= 1)
            acc[o] += __shfl_down_sync(0xffffffffu, acc[o], off, 16);
    }
    if (jx == 0) {
#pragma unroll
        for (int o = 0; o < 8; o++) s_h2s[iy][o] = acc[o];
    }
    __syncthreads();

    // ================= GRU epilogue (16 thr per node) =================
    int nl = tid >> 4, t = tid & 15;
    int node = b * Nc + i0 + nl;

    // phase 0: stage g; gru input (m_sum via W3, plus r/Sigma)
    sg[nl][t] = g_g[node * 16 + t];
    if (t < 8) {
        float m = s_bp3[t] * (float)(Nc - 1);
#pragma unroll
        for (int q = 0; q < 8; q++)
            m = fmaf(s_wp3[t * 9 + q], s_h2s[nl][q], m);
        sgin[nl][t] = m;
    } else if (t == 8) {
        sgin[nl][8] = r[node];
    } else if (t == 9) {
        sgin[nl][9] = Sigma[node];
    }
    __syncthreads();

    // phase 1: one gate per thread
    {
        float ir = s_bih[t],      hr = s_bhh[t];
        float iz = s_bih[16 + t], hz = s_bhh[16 + t];
        float in_ = s_bih[32 + t], hn = s_bhh[32 + t];
#pragma unroll
        for (int k = 0; k < 10; k++) {
            float x = sgin[nl][k];
            ir  = fmaf(s_wih[t * 10 + k],        x, ir);
            iz  = fmaf(s_wih[(16 + t) * 10 + k], x, iz);
            in_ = fmaf(s_wih[(32 + t) * 10 + k], x, in_);
        }
#pragma unroll
        for (int k = 0; k < 16; k++) {
            float x = sg[nl][k];
            hr = fmaf(s_whh[t * 17 + k],        x, hr);
            hz = fmaf(s_whh[(16 + t) * 17 + k], x, hz);
            hn = fmaf(s_whh[(32 + t) * 17 + k], x, hn);
        }
        float rr = sigmoidf_fast(ir + hr);
        float zz = sigmoidf_fast(iz + hz);
        float nn = tanhf_fast(in_ + rr * hn);
        float gv = sg[nl][t];
        float gn = (1.f - zz) * nn + zz * gv;
        sgn[nl][t] = gn;
        g_g[node * 16 + t] = gn;
    }
    __syncthreads();

    // phase 2: u = W_up g + b
    if (t < 8) {
        float uv = s_bup[t];
#pragma unroll
        for (int k = 0; k < 16; k++) uv = fmaf(s_wup[t * 17 + k], sgn[nl][k], uv);
        su[nl][t] = uv;
    }
    __syncthreads();

    if (!last) {
        // phase 3: a,c for next layer -> write buffer
        float sig = sigma2[b];
        float av = s_bp1[t] + s_wp1[t * 18 + 17] * sig;
        float cv = 0.f;
#pragma unroll
        for (int k = 0; k < 8; k++) {
            float uv = su[nl][k];
            av = fmaf(s_wp1[t * 18 + k], uv, av);
            cv = fmaf(s_wp1[t * 18 + 8 + k], uv, cv);
        }
        g_ab[wr][node * 16 + t] = av;
        g_cb[wr][node * 16 + t] = cv;
    } else {
        // ============== fused readout ==============
        // h1 = relu(W_r1 u + b): one element per thread
        {
            float a = s_br1[t];
#pragma unroll
            for (int k = 0; k < 8; k++) a = fmaf(s_r1[t * 8 + k], su[nl][k], a);
            sh1[nl][t] = fmaxf(a, 0.f);
        }
        __syncthreads();
        // h2 = relu(W_r2 h1 + b): t<8
        if (t < 8) {
            float a = s_br2[t];
#pragma unroll
            for (int k = 0; k < 16; k++) a = fmaf(s_r2[t * 16 + k], sh1[nl][k], a);
            sgin[nl][t] = fmaxf(a, 0.f);  // reuse sgin as h2 store
        }
        __syncthreads();
        // logits + softmax: t==0 does all 4
        if (t == 0) {
            float lg[4];
#pragma unroll
            for (int o = 0; o < 4; o++) {
                float a = s_br3[o];
#pragma unroll
                for (int k = 0; k < 8; k++) a = fmaf(s_r3[o * 8 + k], sgin[nl][k], a);
                lg[o] = a;
            }
            float mx = fmaxf(fmaxf(lg[0], lg[1]), fmaxf(lg[2], lg[3]));
            float e0 = __expf(lg[0] - mx), e1 = __expf(lg[1] - mx),
                  e2 = __expf(lg[2] - mx), e3 = __expf(lg[3] - mx);
            float inv = __fdividef(1.f, e0 + e1 + e2 + e3);
            out[node * 4 + 0] = e0 * inv;
            out[node * 4 + 1] = e1 * inv;
            out[node * 4 + 2] = e2 * inv;
            out[node * 4 + 3] = e3 * inv;
        }
        // u and g outputs
        if (t < 8) out[BNc * 4 + node * 8 + t] = su[nl][t];
        out[BNc * 12 + node * 16 + t] = sgn[nl][t];
    }
}

// ============================================================
extern "C" void kernel_launch(void* const* d_in, const int* in_sizes, int n_in,
                              void* d_out, int out_size) {
    const float* y      = (const float*)d_in[0];
    const float* A      = (const float*)d_in[1];
    const float* sigma2 = (const float*)d_in[2];
    const float* r      = (const float*)d_in[3];
    const float* Sigma  = (const float*)d_in[4];
    const float* w_init = (const float*)d_in[5];
    const float* b_init = (const float*)d_in[6];
    const float* w_p1   = (const float*)d_in[7];
    const float* b_p1   = (const float*)d_in[8];
    const float* w_p2   = (const float*)d_in[9];
    const float* b_p2   = (const float*)d_in[10];
    const float* w_p3   = (const float*)d_in[11];
    const float* b_p3   = (const float*)d_in[12];
    const float* w_ih   = (const float*)d_in[13];
    const float* b_ih   = (const float*)d_in[14];
    const float* w_hh   = (const float*)d_in[15];
    const float* b_hh   = (const float*)d_in[16];
    const float* w_up   = (const float*)d_in[17];
    const float* b_up   = (const float*)d_in[18];
    const float* w_r1   = (const float*)d_in[19];
    const float* b_r1   = (const float*)d_in[20];
    const float* w_r2   = (const float*)d_in[21];
    const float* b_r2   = (const float*)d_in[22];
    const float* w_r3   = (const float*)d_in[23];
    const float* b_r3   = (const float*)d_in[24];

    gram_kernel<<<dim3(36, Bc), 256>>>(A);
    init_kernel<<<dim3(Nc / 128, Bc), 128>>>(A, y, sigma2, w_init, b_init, w_p1, b_p1);
    for (int l = 0; l < 2; l++) {
        pair_fused<<<dim3(Nc / 16, Bc), 256>>>(
            w_p1, b_p1, w_p2, b_p2, w_p3, b_p3, w_ih, b_ih, w_hh, b_hh,
            w_up, b_up, r, Sigma, sigma2,
            w_r1, b_r1, w_r2, b_r2, w_r3, b_r3,
            (float*)d_out, l);
    }
}